// round 14
// baseline (speedup 1.0000x reference)
#include <cuda_runtime.h>
#include <cuda_bf16.h>
#include <cstdint>

#define NN   50000
#define NE   500000
#define NGR  64
#define FUS_BLOCKS ((NE + 127) / 128)
#define EDGE_BLKS ((NE + 255) / 256)

// ---------------- device scratch (zero-initialized at load; cleanup re-zeros) ----------------
__device__ __align__(16) __nv_bfloat16 g_hb[(size_t)NE * 64];    // 64 MB, in-place
__device__ __align__(16) __nv_bfloat16 g_aggb[(size_t)NN * 64];  // 6.4 MB bf16 node agg
__device__ int   g_deg[NN];
__device__ int   g_cursor[NN];
__device__ float g_s[NN];
__device__ int   g_csr_off[NN + 1];
__device__ int   g_csr_edges[2 * NE];           // pe (for agg64)
__device__ __align__(8) int2 g_csr_oi[2 * NE];  // {orig_edge, imp bits} (for agg1)
__device__ __align__(8) int2 g_ei01p[NE];       // {n0, n1}
__device__ int   g_gcnt[NGR];
__device__ int   g_gcur[NGR];
__device__ int   g_gstart[NGR + 1];
__device__ int   g_eorig[NE];
__device__ int   g_ebp[NE];
__device__ float g_impp[NE];
__device__ float g_dinvp[NE];
__device__ __align__(16) unsigned char g_Wb[3][2][8192];  // swizzled bf16 W (hi,lo)
__device__ int   g_is64;
__device__ volatile int g_flag[64];
__device__ volatile int g_pref[64];
__device__ int   g_done;

// ---------------- helpers ----------------
__device__ __forceinline__ uint32_t smem_to_u32(const void* p) {
    uint32_t a;
    asm("{ .reg .u64 t; cvta.to.shared.u64 t, %1; cvt.u32.u64 %0, t; }" : "=r"(a) : "l"(p));
    return a;
}
__device__ __forceinline__ unsigned pk2(float a, float b) {
    __nv_bfloat162 t = __floats2bfloat162_rn(a, b);
    return reinterpret_cast<unsigned&>(t);
}
__device__ __forceinline__ void upk8(uint4 u, float* d) {
    unsigned w[4] = {u.x, u.y, u.z, u.w};
    #pragma unroll
    for (int i = 0; i < 4; i++) {
        unsigned ww = w[i];
        __nv_bfloat162 t = reinterpret_cast<__nv_bfloat162&>(ww);
        float2 f = __bfloat1622float2(t);
        d[2 * i] = f.x; d[2 * i + 1] = f.y;
    }
}
__device__ __forceinline__ unsigned sw128(unsigned off) { return off ^ ((off >> 3) & 0x70); }

__device__ __forceinline__ int LD_IDX(const int* __restrict__ p, long long i) {
    return g_is64 ? p[2 * i] : p[(size_t)i];
}

__device__ __forceinline__ void ldsm_x4(uint32_t& a0, uint32_t& a1, uint32_t& a2, uint32_t& a3,
                                        uint32_t addr) {
    asm volatile("ldmatrix.sync.aligned.m8n8.x4.shared.b16 {%0,%1,%2,%3}, [%4];"
                 : "=r"(a0), "=r"(a1), "=r"(a2), "=r"(a3) : "r"(addr));
}
__device__ __forceinline__ void ldsm_x2(uint32_t& b0, uint32_t& b1, uint32_t addr) {
    asm volatile("ldmatrix.sync.aligned.m8n8.x2.shared.b16 {%0,%1}, [%2];"
                 : "=r"(b0), "=r"(b1) : "r"(addr));
}
__device__ __forceinline__ void mma16816(float* c, uint32_t a0, uint32_t a1, uint32_t a2,
                                         uint32_t a3, uint32_t b0, uint32_t b1) {
    asm volatile("mma.sync.aligned.m16n8k16.row.col.f32.bf16.bf16.f32 "
                 "{%0,%1,%2,%3}, {%4,%5,%6,%7}, {%8,%9}, {%0,%1,%2,%3};"
                 : "+f"(c[0]), "+f"(c[1]), "+f"(c[2]), "+f"(c[3])
                 : "r"(a0), "r"(a1), "r"(a2), "r"(a3), "r"(b0), "r"(b1));
}

// ---------------- K1: deg + gcnt + out-zero + detect + wprep ----------------
__global__ __launch_bounds__(256) void deg_all(float* __restrict__ out,
                                               const int* __restrict__ eidx,
                                               const int* __restrict__ batch,
                                               const float* __restrict__ W0,
                                               const float* __restrict__ W1,
                                               const float* __restrict__ W2) {
    int b = blockIdx.x, tid = threadIdx.x;
    if (b < EDGE_BLKS) {
        __shared__ int sh[NGR];
        __shared__ int s_is64;
        if (tid < NGR) sh[tid] = 0;
        if (tid == 0) {
            int z = 0;
            #pragma unroll
            for (int i = 0; i < 64; i++) z |= eidx[2 * i + 1];
            s_is64 = (z == 0) ? 1 : 0;
            if (b == 0) g_is64 = s_is64;
        }
        __syncthreads();
        int is64 = s_is64;
        int e = b * 256 + tid;
        if (e < NE) {
            int a = is64 ? eidx[2 * e] : eidx[e];
            int c = is64 ? eidx[2 * ((long long)NE + e)] : eidx[NE + e];
            atomicAdd(&g_deg[a], 1);
            atomicAdd(&g_deg[c], 1);
            int g = is64 ? batch[2 * a] : batch[a];
            atomicAdd(&sh[g], 1);
        }
        __syncthreads();
        if (tid < NGR && sh[tid] > 0) atomicAdd(&g_gcnt[tid], sh[tid]);
    } else if (b < EDGE_BLKS + 48) {
        int i = (b - EDGE_BLKS) * 256 + tid;
        if (i < NGR * 192) out[i] = 0.f;
    } else {
        int l = b - (EDGE_BLKS + 48);
        const float* W = (l == 0) ? W0 : ((l == 1) ? W1 : W2);
        int KIN = (l == 0) ? 32 : 64;
        for (int i = tid; i < 4096; i += 256) {
            int n = i >> 6, k = i & 63;
            float w = (k < KIN) ? W[k * 64 + n] : 0.f;
            __nv_bfloat16 hi = __float2bfloat16(w);
            __nv_bfloat16 lo = __float2bfloat16(w - __bfloat162float(hi));
            unsigned sw = sw128((unsigned)(n * 128 + k * 2));
            *reinterpret_cast<__nv_bfloat16*>(&g_Wb[l][0][sw]) = hi;
            *reinterpret_cast<__nv_bfloat16*>(&g_Wb[l][1][sw]) = lo;
        }
    }
}

// ---------------- K2: scan (decoupled lookback) + node + gstart + edge pass ----------------
__global__ __launch_bounds__(1024) void scanedge_kernel(const int* __restrict__ eidx,
                                                        const int* __restrict__ batch,
                                                        const float* __restrict__ nimp) {
    __shared__ int ws[32];
    __shared__ int wo[32];
    __shared__ int s_total;
    __shared__ int s_pref;
    int tid = threadIdx.x, lane = tid & 31, w = tid >> 5;
    int bid = blockIdx.x;
    int i = bid * 1024 + tid;
    int v = (i < NN) ? g_deg[i] : 0;
    int inc = v;
    #pragma unroll
    for (int o = 1; o < 32; o <<= 1) {
        int u = __shfl_up_sync(0xffffffffu, inc, o);
        if (lane >= o) inc += u;
    }
    if (lane == 31) ws[w] = inc;
    __syncthreads();
    if (w == 0) {
        int x = ws[lane], xi = x;
        #pragma unroll
        for (int o = 1; o < 32; o <<= 1) {
            int u = __shfl_up_sync(0xffffffffu, xi, o);
            if (lane >= o) xi += u;
        }
        wo[lane] = xi - x;
        if (lane == 31) s_total = xi;
    }
    __syncthreads();
    if (tid == 0) {
        int p = 0;
        if (bid > 0) {
            while (g_flag[bid - 1] == 0) { }
            p = g_pref[bid - 1];
        }
        g_pref[bid] = p + s_total;
        __threadfence();
        g_flag[bid] = 1;
        s_pref = p;
    }
    __syncthreads();
    if (i < NN) {
        g_csr_off[i] = s_pref + wo[w] + inc - v;
        g_s[i] = (v > 1) ? 1.0f / (float)v : 0.0f;
    }
    if (bid == 48 && tid == 0) {
        while (g_flag[48] == 0) { }
        g_csr_off[NN] = g_pref[48];
        int r2 = 0;
        for (int g = 0; g < NGR; g++) { g_gstart[g] = r2; r2 += g_gcnt[g]; }
        g_gstart[NGR] = r2;
    }
    __syncthreads();
    if (tid == 0) {
        __threadfence();
        atomicAdd(&g_done, 1);
        while (*(volatile int*)&g_done < 49) { }
    }
    __syncthreads();
    // ---- edge pass (grid-stride over 49x1024 threads) ----
    for (long long e = bid * 1024 + tid; e < NE; e += 49 * 1024) {
        int a = LD_IDX(eidx, e);
        int b = LD_IDX(eidx, (long long)NE + e);
        int g = LD_IDX(batch, a);
        int pe = g_gstart[g] + atomicAdd(&g_gcur[g], 1);
        float im = fminf(nimp[a], nimp[b]);
        g_ei01p[pe] = make_int2(a, b);
        g_eorig[pe] = (int)e;
        g_ebp[pe]   = g;
        g_impp[pe]  = im;
        int ka = (g_deg[a] != 1) ? 1 : 0;
        int kb = (g_deg[b] != 1) ? 1 : 0;
        g_dinvp[pe] = 1.0f / (float)(1 + ka + kb);
        int2 oi = make_int2((int)e, __float_as_int(im));
        int p = atomicAdd(&g_cursor[a], 1);
        int sa = g_csr_off[a] + p;
        g_csr_edges[sa] = pe;
        g_csr_oi[sa] = oi;
        p = atomicAdd(&g_cursor[b], 1);
        int sb2 = g_csr_off[b] + p;
        g_csr_edges[sb2] = pe;
        g_csr_oi[sb2] = oi;
    }
}

// ---------------- K3: agg1 (2-level chain via packed csr_oi) ----------------
__global__ __launch_bounds__(256) void agg1_kernel(const float* __restrict__ ea) {
    int n = blockIdx.x * 8 + (threadIdx.x >> 5);
    if (n >= NN) return;
    int l = threadIdx.x & 31;
    float s = g_s[n];
    float acc = 0.f;
    if (s != 0.f) {
        int i = g_csr_off[n], e = g_csr_off[n + 1];
        for (; i + 8 <= e; i += 8) {
            float x[8];
            #pragma unroll
            for (int j = 0; j < 8; j++) {
                int2 oi = g_csr_oi[i + j];
                x[j] = __int_as_float(oi.y) * ea[(size_t)oi.x * 32 + l];
            }
            acc += ((x[0] + x[1]) + (x[2] + x[3])) + ((x[4] + x[5]) + (x[6] + x[7]));
        }
        for (; i < e; i++) {
            int2 oi = g_csr_oi[i];
            acc += __int_as_float(oi.y) * ea[(size_t)oi.x * 32 + l];
        }
    }
    g_aggb[(size_t)n * 32 + l] = __float2bfloat16(s * acc);   // compact 32-col layout
}

__global__ __launch_bounds__(256) void agg64_kernel() {
    const __nv_bfloat16* __restrict__ hb = g_hb;
    int n = blockIdx.x * 8 + (threadIdx.x >> 5);
    if (n >= NN) return;
    int l = threadIdx.x & 31;
    float s = g_s[n];
    float a0 = 0.f, a1 = 0.f;
    if (s != 0.f) {
        int i = g_csr_off[n], e = g_csr_off[n + 1];
        for (; i + 8 <= e; i += 8) {
            float2 f[8];
            #pragma unroll
            for (int j = 0; j < 8; j++) {
                int p = g_csr_edges[i + j];
                f[j] = __bfloat1622float2(
                    reinterpret_cast<const __nv_bfloat162*>(hb + (size_t)p * 64)[l]);
            }
            a0 += ((f[0].x + f[1].x) + (f[2].x + f[3].x)) + ((f[4].x + f[5].x) + (f[6].x + f[7].x));
            a1 += ((f[0].y + f[1].y) + (f[2].y + f[3].y)) + ((f[4].y + f[5].y) + (f[6].y + f[7].y));
        }
        for (; i < e; i++) {
            int p = g_csr_edges[i];
            float2 f0 = __bfloat1622float2(
                reinterpret_cast<const __nv_bfloat162*>(hb + (size_t)p * 64)[l]);
            a0 += f0.x; a1 += f0.y;
        }
    }
    unsigned v = pk2(s * a0, s * a1);
    reinterpret_cast<unsigned*>(g_aggb)[(size_t)n * 32 + l] = v;  // full 64-col layout
}

// ---------------- fused: stage-t + HMMA (4x2 warp grid) + epilogue ----------------
#define SMEM_A_OFF   0
#define SMEM_BH_OFF  16384
#define SMEM_BS_OFF  32768
#define SMEM_PL_OFF  33024
#define SMEM_TOTAL   34048

__device__ __forceinline__ void stage8(uint4 H, uint4 A, uint4 B, float dv, unsigned* o) {
    float hh[8], a0[8], a1[8];
    upk8(H, hh); upk8(A, a0); upk8(B, a1);
    #pragma unroll
    for (int j = 0; j < 4; j++)
        o[j] = pk2(dv * (hh[2 * j] + a0[2 * j] + a1[2 * j]),
                   dv * (hh[2 * j + 1] + a0[2 * j + 1] + a1[2 * j + 1]));
}

template <int LAYER, bool WRITE_H>
__global__ __launch_bounds__(256, 5) void fused_kernel(const float* __restrict__ bias,
                                                       const float* __restrict__ ea,
                                                       float* __restrict__ out) {
    extern __shared__ char smem[];
    uint32_t sb = smem_to_u32(smem);
    float* spool = reinterpret_cast<float*>(smem + SMEM_PL_OFF);  // [8 warps][32 cols]
    int tid = threadIdx.x, wid = tid >> 5, lane = tid & 31;
    int e0 = blockIdx.x * 128;

    {   // W (hi+lo 16KB, pre-swizzled)
        const uint4* src = reinterpret_cast<const uint4*>(&g_Wb[LAYER - 1][0][0]);
        uint4* dst = reinterpret_cast<uint4*>(smem + SMEM_BH_OFF);
        #pragma unroll
        for (int i = 0; i < 4; i++) dst[tid + 256 * i] = src[tid + 256 * i];
    }
    if (tid < 64) reinterpret_cast<float*>(smem + SMEM_BS_OFF)[tid] = bias[tid];

    // ---- stage t tile (128 rows x K bf16, swizzled 128B rows) ----
    if (LAYER == 1) {
        int r = tid >> 1, hf = tid & 1, c0 = hf * 16;
        long long e = e0 + r;
        float v[16];
        if (e < NE) {
            int2 nn = g_ei01p[e];
            int og = g_eorig[e];
            float dv = g_dinvp[e], im = g_impp[e];
            const float4* pa = reinterpret_cast<const float4*>(ea + (size_t)og * 32 + c0);
            const uint4* q0 = reinterpret_cast<const uint4*>(g_aggb + (size_t)nn.x * 32 + c0);
            const uint4* q1 = reinterpret_cast<const uint4*>(g_aggb + (size_t)nn.y * 32 + c0);
            float a0[16], a1[16];
            upk8(q0[0], a0); upk8(q0[1], a0 + 8);
            upk8(q1[0], a1); upk8(q1[1], a1 + 8);
            #pragma unroll
            for (int q = 0; q < 4; q++) {
                float4 a = pa[q];
                v[q * 4 + 0] = dv * (im * a.x + a0[q * 4 + 0] + a1[q * 4 + 0]);
                v[q * 4 + 1] = dv * (im * a.y + a0[q * 4 + 1] + a1[q * 4 + 1]);
                v[q * 4 + 2] = dv * (im * a.z + a0[q * 4 + 2] + a1[q * 4 + 2]);
                v[q * 4 + 3] = dv * (im * a.w + a0[q * 4 + 3] + a1[q * 4 + 3]);
            }
        } else {
            #pragma unroll
            for (int q = 0; q < 16; q++) v[q] = 0.f;
        }
        unsigned off = (unsigned)(r * 128 + c0 * 2);
        *reinterpret_cast<uint4*>(smem + SMEM_A_OFF + sw128(off)) =
            make_uint4(pk2(v[0], v[1]), pk2(v[2], v[3]), pk2(v[4], v[5]), pk2(v[6], v[7]));
        *reinterpret_cast<uint4*>(smem + SMEM_A_OFF + sw128(off + 16)) =
            make_uint4(pk2(v[8], v[9]), pk2(v[10], v[11]), pk2(v[12], v[13]), pk2(v[14], v[15]));
        // no zero padding: layer-1 MMA (KSTEPS=2) never reads bytes 64..127
    } else {
        #pragma unroll
        for (int pass = 0; pass < 2; pass++) {
            int r = (tid >> 2) + pass * 64;
            int q = tid & 3, c0 = q * 16;
            long long e = e0 + r;
            unsigned o0[4], o1[4];
            if (e < NE) {
                int2 nn = g_ei01p[e];
                float dv = g_dinvp[e];
                const uint4* ph = reinterpret_cast<const uint4*>(g_hb + (size_t)e * 64 + c0);
                const uint4* q0 = reinterpret_cast<const uint4*>(g_aggb + (size_t)nn.x * 64 + c0);
                const uint4* q1 = reinterpret_cast<const uint4*>(g_aggb + (size_t)nn.y * 64 + c0);
                uint4 H0 = ph[0], H1 = ph[1];
                uint4 A0 = q0[0], A1 = q0[1];
                uint4 B0 = q1[0], B1 = q1[1];
                stage8(H0, A0, B0, dv, o0);
                stage8(H1, A1, B1, dv, o1);
            } else {
                #pragma unroll
                for (int j = 0; j < 4; j++) { o0[j] = 0u; o1[j] = 0u; }
            }
            unsigned off = (unsigned)(r * 128 + c0 * 2);
            *reinterpret_cast<uint4*>(smem + SMEM_A_OFF + sw128(off)) =
                make_uint4(o0[0], o0[1], o0[2], o0[3]);
            *reinterpret_cast<uint4*>(smem + SMEM_A_OFF + sw128(off + 16)) =
                make_uint4(o1[0], o1[1], o1[2], o1[3]);
        }
    }
    __syncthreads();

    // ---- warp-level HMMA: 4x2 warp grid, each warp 32 rows x 32 cols ----
    constexpr int KSTEPS = (LAYER == 1) ? 2 : 4;
    int wr = wid & 3, wc = wid >> 2;
    float acc[2][4][4];
    #pragma unroll
    for (int m = 0; m < 2; m++)
        #pragma unroll
        for (int nt = 0; nt < 4; nt++) {
            acc[m][nt][0] = 0.f; acc[m][nt][1] = 0.f;
            acc[m][nt][2] = 0.f; acc[m][nt][3] = 0.f;
        }
    unsigned acol = (unsigned)(lane >> 4) * 16;
    unsigned alr  = (unsigned)(lane & 15);
    unsigned bsel = (unsigned)((lane >> 3) & 1) * 16;
    unsigned blr  = (unsigned)(lane & 7);

    #pragma unroll
    for (int kk = 0; kk < KSTEPS; kk++) {
        unsigned kb = (unsigned)kk * 32;
        uint32_t a[2][4];
        #pragma unroll
        for (int m = 0; m < 2; m++) {
            unsigned arow = (unsigned)(wr * 32 + m * 16) + alr;
            ldsm_x4(a[m][0], a[m][1], a[m][2], a[m][3],
                    sb + SMEM_A_OFF + sw128(arow * 128 + acol + kb));
        }
        #pragma unroll
        for (int pass = 0; pass < 2; pass++) {
            uint32_t wb = sb + SMEM_BH_OFF + (unsigned)pass * 8192u;
            #pragma unroll
            for (int nt = 0; nt < 4; nt++) {
                unsigned brow = (unsigned)(wc * 32 + nt * 8) + blr;
                uint32_t b0, b1;
                ldsm_x2(b0, b1, wb + sw128(brow * 128 + kb + bsel));
                mma16816(acc[0][nt], a[0][0], a[0][1], a[0][2], a[0][3], b0, b1);
                mma16816(acc[1][nt], a[1][0], a[1][1], a[1][2], a[1][3], b0, b1);
            }
        }
    }

    // ---- epilogue: bias + relu + imp; shfl-based pool; optional bf16 writeback ----
    const int LOFF = (LAYER - 1) * 64;
    {
        int g = lane >> 2, q = lane & 3;
        int gA = g_ebp[e0];
        long long elast = (long long)e0 + 127 < NE ? (long long)e0 + 127 : NE - 1;
        bool uni = (g_ebp[elast] == gA);       // block entirely within one graph
        const float* sB = reinterpret_cast<const float*>(smem + SMEM_BS_OFF);
        float pacc[4][2];
        #pragma unroll
        for (int nt = 0; nt < 4; nt++) { pacc[nt][0] = 0.f; pacc[nt][1] = 0.f; }
        #pragma unroll
        for (int m = 0; m < 2; m++) {
            long long ra = e0 + wr * 32 + m * 16 + g, rb = ra + 8;
            bool oka = ra < NE, okb = rb < NE;
            float ia = oka ? g_impp[ra] : 0.f;
            float ib = okb ? g_impp[rb] : 0.f;
            int ga = oka ? g_ebp[ra] : gA;
            int gb = okb ? g_ebp[rb] : gA;
            #pragma unroll
            for (int nt = 0; nt < 4; nt++) {
                int c0 = wc * 32 + nt * 8 + q * 2;
                float bz0 = sB[c0], bz1 = sB[c0 + 1];
                float va0 = fmaxf(acc[m][nt][0] + bz0, 0.f) * ia;
                float va1 = fmaxf(acc[m][nt][1] + bz1, 0.f) * ia;
                float vb0 = fmaxf(acc[m][nt][2] + bz0, 0.f) * ib;
                float vb1 = fmaxf(acc[m][nt][3] + bz1, 0.f) * ib;
                pacc[nt][0] += va0 + vb0;
                pacc[nt][1] += va1 + vb1;
                if (!uni) {   // rare: block straddles a graph boundary
                    if (oka) { atomicAdd(&out[ga * 192 + LOFF + c0], va0);
                               atomicAdd(&out[ga * 192 + LOFF + c0 + 1], va1); }
                    if (okb) { atomicAdd(&out[gb * 192 + LOFF + c0], vb0);
                               atomicAdd(&out[gb * 192 + LOFF + c0 + 1], vb1); }
                }
                if (WRITE_H) {
                    int rrow = wr * 32 + m * 16 + g;
                    *reinterpret_cast<unsigned*>(smem + sw128((unsigned)(rrow * 128 + c0 * 2))) =
                        pk2(va0, va1);
                    *reinterpret_cast<unsigned*>(smem + sw128((unsigned)((rrow + 8) * 128 + c0 * 2))) =
                        pk2(vb0, vb1);
                }
            }
        }
        if (uni) {
            #pragma unroll
            for (int o = 4; o < 32; o <<= 1) {
                #pragma unroll
                for (int nt = 0; nt < 4; nt++) {
                    pacc[nt][0] += __shfl_xor_sync(0xffffffffu, pacc[nt][0], o);
                    pacc[nt][1] += __shfl_xor_sync(0xffffffffu, pacc[nt][1], o);
                }
            }
            if (g == 0) {   // lanes 0..3 hold warp column sums (32 cols per warp)
                #pragma unroll
                for (int nt = 0; nt < 4; nt++) {
                    spool[wid * 32 + nt * 8 + q * 2]     = pacc[nt][0];
                    spool[wid * 32 + nt * 8 + q * 2 + 1] = pacc[nt][1];
                }
            }
        }
        __syncthreads();
        if (uni && tid < 64) {
            int c = tid & 31, wcn = tid >> 5;
            float s = 0.f;
            #pragma unroll
            for (int j = 0; j < 4; j++) s += spool[(wcn * 4 + j) * 32 + c];
            atomicAdd(&out[gA * 192 + LOFF + wcn * 32 + c], s);
        }
    }

    if (WRITE_H) {
        int r = tid >> 1, hf = tid & 1;
        long long e = e0 + r;
        if (e < NE) {
            uint4 x0 = *reinterpret_cast<const uint4*>(smem + sw128((unsigned)(r * 128 + hf * 64)));
            uint4 x1 = *reinterpret_cast<const uint4*>(smem + sw128((unsigned)(r * 128 + hf * 64 + 16)));
            uint4 x2 = *reinterpret_cast<const uint4*>(smem + sw128((unsigned)(r * 128 + hf * 64 + 32)));
            uint4 x3 = *reinterpret_cast<const uint4*>(smem + sw128((unsigned)(r * 128 + hf * 64 + 48)));
            uint4* dst = reinterpret_cast<uint4*>(g_hb + (size_t)e * 64 + hf * 32);
            dst[0] = x0; dst[1] = x1; dst[2] = x2; dst[3] = x3;
        }
    }
}

// ---------------- tail: reset counters for next replay ----------------
__global__ void cleanup_kernel() {
    int i = blockIdx.x * 256 + threadIdx.x;
    if (i < NN) { g_deg[i] = 0; g_cursor[i] = 0; }
    if (i < NGR) { g_gcnt[i] = 0; g_gcur[i] = 0; g_flag[i] = 0; }
    if (i == 0) g_done = 0;
}

// ---------------- launch ----------------
extern "C" void kernel_launch(void* const* d_in, const int* in_sizes, int n_in,
                              void* d_out, int out_size) {
    const float* edge_attr = (const float*)d_in[1];
    const int*   eidx      = (const int*)d_in[2];
    const int*   batch     = (const int*)d_in[3];
    const float* nimp      = (const float*)d_in[4];
    const float* W0 = (const float*)d_in[5];
    const float* b0 = (const float*)d_in[6];
    const float* W1 = (const float*)d_in[7];
    const float* b1 = (const float*)d_in[8];
    const float* W2 = (const float*)d_in[9];
    const float* b2 = (const float*)d_in[10];
    float* out = (float*)d_out;

    const int AGG_BLKS = (NN + 7) / 8;

    deg_all<<<EDGE_BLKS + 48 + 3, 256>>>(out, eidx, batch, W0, W1, W2);   // #1
    scanedge_kernel<<<49, 1024>>>(eidx, batch, nimp);                     // #2
    agg1_kernel<<<AGG_BLKS, 256>>>(edge_attr);                            // #3
    fused_kernel<1, true><<<FUS_BLOCKS, 256, SMEM_TOTAL>>>(b0, edge_attr, out);  // #4 <- ncu
    agg64_kernel<<<AGG_BLKS, 256>>>();
    fused_kernel<2, true><<<FUS_BLOCKS, 256, SMEM_TOTAL>>>(b1, nullptr, out);
    agg64_kernel<<<AGG_BLKS, 256>>>();
    fused_kernel<3, false><<<FUS_BLOCKS, 256, SMEM_TOTAL>>>(b2, nullptr, out);
    cleanup_kernel<<<196, 256>>>();
}

// round 15
// speedup vs baseline: 1.0526x; 1.0526x over previous
#include <cuda_runtime.h>
#include <cuda_bf16.h>
#include <cstdint>

#define NN   50000
#define NE   500000
#define NGR  64
#define FUS_BLOCKS ((NE + 127) / 128)
#define EDGE_BLKS ((NE + 255) / 256)

// ---------------- device scratch (zero-initialized at load; cleanup re-zeros) ----------------
__device__ __align__(16) __nv_bfloat16 g_hb[(size_t)NE * 64];    // 64 MB, in-place
__device__ __align__(16) __nv_bfloat16 g_aggb[(size_t)NN * 64];  // 6.4 MB bf16 node agg
__device__ int   g_deg[NN];
__device__ int   g_cursor[NN];
__device__ float g_s[NN];
__device__ int   g_csr_off[NN + 1];
__device__ int   g_csr_edges[2 * NE];           // pe (for agg64)
__device__ __align__(8) int2 g_csr_oi[2 * NE];  // {orig_edge, imp bits} (for agg1)
__device__ __align__(8) int2 g_ei01p[NE];       // {n0, n1}
__device__ int   g_gcnt[NGR];
__device__ int   g_gcur[NGR];
__device__ int   g_gstart[NGR + 1];
__device__ int   g_eorig[NE];
__device__ int   g_ebp[NE];
__device__ float g_impp[NE];
__device__ float g_dinvp[NE];
__device__ __align__(16) unsigned char g_Wb[3][2][8192];  // swizzled bf16 W (hi,lo)
__device__ int   g_is64;
__device__ volatile int g_flag[64];
__device__ volatile int g_pref[64];
__device__ int   g_done;

// ---------------- helpers ----------------
__device__ __forceinline__ uint32_t smem_to_u32(const void* p) {
    uint32_t a;
    asm("{ .reg .u64 t; cvta.to.shared.u64 t, %1; cvt.u32.u64 %0, t; }" : "=r"(a) : "l"(p));
    return a;
}
__device__ __forceinline__ unsigned pk2(float a, float b) {
    __nv_bfloat162 t = __floats2bfloat162_rn(a, b);
    return reinterpret_cast<unsigned&>(t);
}
__device__ __forceinline__ void upk8(uint4 u, float* d) {
    unsigned w[4] = {u.x, u.y, u.z, u.w};
    #pragma unroll
    for (int i = 0; i < 4; i++) {
        unsigned ww = w[i];
        __nv_bfloat162 t = reinterpret_cast<__nv_bfloat162&>(ww);
        float2 f = __bfloat1622float2(t);
        d[2 * i] = f.x; d[2 * i + 1] = f.y;
    }
}
__device__ __forceinline__ unsigned sw128(unsigned off) { return off ^ ((off >> 3) & 0x70); }

__device__ __forceinline__ int LD_IDX(const int* __restrict__ p, long long i) {
    return g_is64 ? p[2 * i] : p[(size_t)i];
}

__device__ __forceinline__ void ldsm_x4(uint32_t& a0, uint32_t& a1, uint32_t& a2, uint32_t& a3,
                                        uint32_t addr) {
    asm volatile("ldmatrix.sync.aligned.m8n8.x4.shared.b16 {%0,%1,%2,%3}, [%4];"
                 : "=r"(a0), "=r"(a1), "=r"(a2), "=r"(a3) : "r"(addr));
}
__device__ __forceinline__ void mma16816(float* c, uint32_t a0, uint32_t a1, uint32_t a2,
                                         uint32_t a3, uint32_t b0, uint32_t b1) {
    asm volatile("mma.sync.aligned.m16n8k16.row.col.f32.bf16.bf16.f32 "
                 "{%0,%1,%2,%3}, {%4,%5,%6,%7}, {%8,%9}, {%0,%1,%2,%3};"
                 : "+f"(c[0]), "+f"(c[1]), "+f"(c[2]), "+f"(c[3])
                 : "r"(a0), "r"(a1), "r"(a2), "r"(a3), "r"(b0), "r"(b1));
}

// ---------------- K1: deg + gcnt + out-zero + detect + wprep ----------------
__global__ __launch_bounds__(256) void deg_all(float* __restrict__ out,
                                               const int* __restrict__ eidx,
                                               const int* __restrict__ batch,
                                               const float* __restrict__ W0,
                                               const float* __restrict__ W1,
                                               const float* __restrict__ W2) {
    int b = blockIdx.x, tid = threadIdx.x;
    if (b < EDGE_BLKS) {
        __shared__ int sh[NGR];
        __shared__ int s_is64;
        if (tid < NGR) sh[tid] = 0;
        if (tid == 0) {
            int z = 0;
            #pragma unroll
            for (int i = 0; i < 64; i++) z |= eidx[2 * i + 1];
            s_is64 = (z == 0) ? 1 : 0;
            if (b == 0) g_is64 = s_is64;
        }
        __syncthreads();
        int is64 = s_is64;
        int e = b * 256 + tid;
        if (e < NE) {
            int a = is64 ? eidx[2 * e] : eidx[e];
            int c = is64 ? eidx[2 * ((long long)NE + e)] : eidx[NE + e];
            atomicAdd(&g_deg[a], 1);
            atomicAdd(&g_deg[c], 1);
            int g = is64 ? batch[2 * a] : batch[a];
            atomicAdd(&sh[g], 1);
        }
        __syncthreads();
        if (tid < NGR && sh[tid] > 0) atomicAdd(&g_gcnt[tid], sh[tid]);
    } else if (b < EDGE_BLKS + 48) {
        int i = (b - EDGE_BLKS) * 256 + tid;
        if (i < NGR * 192) out[i] = 0.f;
    } else {
        int l = b - (EDGE_BLKS + 48);
        const float* W = (l == 0) ? W0 : ((l == 1) ? W1 : W2);
        int KIN = (l == 0) ? 32 : 64;
        for (int i = tid; i < 4096; i += 256) {
            int n = i >> 6, k = i & 63;
            float w = (k < KIN) ? W[k * 64 + n] : 0.f;
            __nv_bfloat16 hi = __float2bfloat16(w);
            __nv_bfloat16 lo = __float2bfloat16(w - __bfloat162float(hi));
            unsigned sw = sw128((unsigned)(n * 128 + k * 2));
            *reinterpret_cast<__nv_bfloat16*>(&g_Wb[l][0][sw]) = hi;
            *reinterpret_cast<__nv_bfloat16*>(&g_Wb[l][1][sw]) = lo;
        }
    }
}

// ---------------- K2: scan (decoupled lookback) + node + gstart + edge pass ----------------
__global__ __launch_bounds__(1024) void scanedge_kernel(const int* __restrict__ eidx,
                                                        const int* __restrict__ batch,
                                                        const float* __restrict__ nimp) {
    __shared__ int ws[32];
    __shared__ int wo[32];
    __shared__ int s_total;
    __shared__ int s_pref;
    int tid = threadIdx.x, lane = tid & 31, w = tid >> 5;
    int bid = blockIdx.x;
    int i = bid * 1024 + tid;
    int v = (i < NN) ? g_deg[i] : 0;
    int inc = v;
    #pragma unroll
    for (int o = 1; o < 32; o <<= 1) {
        int u = __shfl_up_sync(0xffffffffu, inc, o);
        if (lane >= o) inc += u;
    }
    if (lane == 31) ws[w] = inc;
    __syncthreads();
    if (w == 0) {
        int x = ws[lane], xi = x;
        #pragma unroll
        for (int o = 1; o < 32; o <<= 1) {
            int u = __shfl_up_sync(0xffffffffu, xi, o);
            if (lane >= o) xi += u;
        }
        wo[lane] = xi - x;
        if (lane == 31) s_total = xi;
    }
    __syncthreads();
    if (tid == 0) {
        int p = 0;
        if (bid > 0) {
            while (g_flag[bid - 1] == 0) { }
            p = g_pref[bid - 1];
        }
        g_pref[bid] = p + s_total;
        __threadfence();
        g_flag[bid] = 1;
        s_pref = p;
    }
    __syncthreads();
    if (i < NN) {
        g_csr_off[i] = s_pref + wo[w] + inc - v;
        g_s[i] = (v > 1) ? 1.0f / (float)v : 0.0f;
    }
    if (bid == 48 && tid == 0) {
        while (g_flag[48] == 0) { }
        g_csr_off[NN] = g_pref[48];
        int r2 = 0;
        for (int g = 0; g < NGR; g++) { g_gstart[g] = r2; r2 += g_gcnt[g]; }
        g_gstart[NGR] = r2;
    }
    __syncthreads();
    if (tid == 0) {
        __threadfence();
        atomicAdd(&g_done, 1);
        while (*(volatile int*)&g_done < 49) { }
    }
    __syncthreads();
    // ---- edge pass (grid-stride over 49x1024 threads) ----
    for (long long e = bid * 1024 + tid; e < NE; e += 49 * 1024) {
        int a = LD_IDX(eidx, e);
        int b = LD_IDX(eidx, (long long)NE + e);
        int g = LD_IDX(batch, a);
        int pe = g_gstart[g] + atomicAdd(&g_gcur[g], 1);
        float im = fminf(nimp[a], nimp[b]);
        g_ei01p[pe] = make_int2(a, b);
        g_eorig[pe] = (int)e;
        g_ebp[pe]   = g;
        g_impp[pe]  = im;
        int ka = (g_deg[a] != 1) ? 1 : 0;
        int kb = (g_deg[b] != 1) ? 1 : 0;
        g_dinvp[pe] = 1.0f / (float)(1 + ka + kb);
        int2 oi = make_int2((int)e, __float_as_int(im));
        int p = atomicAdd(&g_cursor[a], 1);
        int sa = g_csr_off[a] + p;
        g_csr_edges[sa] = pe;
        g_csr_oi[sa] = oi;
        p = atomicAdd(&g_cursor[b], 1);
        int sb2 = g_csr_off[b] + p;
        g_csr_edges[sb2] = pe;
        g_csr_oi[sb2] = oi;
    }
}

// ---------------- K3: agg1 (2-level chain via packed csr_oi) ----------------
__global__ __launch_bounds__(256) void agg1_kernel(const float* __restrict__ ea) {
    int n = blockIdx.x * 8 + (threadIdx.x >> 5);
    if (n >= NN) return;
    int l = threadIdx.x & 31;
    float s = g_s[n];
    float acc = 0.f;
    if (s != 0.f) {
        int i = g_csr_off[n], e = g_csr_off[n + 1];
        for (; i + 8 <= e; i += 8) {
            float x[8];
            #pragma unroll
            for (int j = 0; j < 8; j++) {
                int2 oi = g_csr_oi[i + j];
                x[j] = __int_as_float(oi.y) * ea[(size_t)oi.x * 32 + l];
            }
            acc += ((x[0] + x[1]) + (x[2] + x[3])) + ((x[4] + x[5]) + (x[6] + x[7]));
        }
        for (; i < e; i++) {
            int2 oi = g_csr_oi[i];
            acc += __int_as_float(oi.y) * ea[(size_t)oi.x * 32 + l];
        }
    }
    g_aggb[(size_t)n * 32 + l] = __float2bfloat16(s * acc);   // compact 32-col layout
}

__global__ __launch_bounds__(256) void agg64_kernel() {
    const __nv_bfloat16* __restrict__ hb = g_hb;
    int n = blockIdx.x * 8 + (threadIdx.x >> 5);
    if (n >= NN) return;
    int l = threadIdx.x & 31;
    float s = g_s[n];
    float a0 = 0.f, a1 = 0.f;
    if (s != 0.f) {
        int i = g_csr_off[n], e = g_csr_off[n + 1];
        for (; i + 8 <= e; i += 8) {
            float2 f[8];
            #pragma unroll
            for (int j = 0; j < 8; j++) {
                int p = g_csr_edges[i + j];
                f[j] = __bfloat1622float2(
                    reinterpret_cast<const __nv_bfloat162*>(hb + (size_t)p * 64)[l]);
            }
            a0 += ((f[0].x + f[1].x) + (f[2].x + f[3].x)) + ((f[4].x + f[5].x) + (f[6].x + f[7].x));
            a1 += ((f[0].y + f[1].y) + (f[2].y + f[3].y)) + ((f[4].y + f[5].y) + (f[6].y + f[7].y));
        }
        for (; i < e; i++) {
            int p = g_csr_edges[i];
            float2 f0 = __bfloat1622float2(
                reinterpret_cast<const __nv_bfloat162*>(hb + (size_t)p * 64)[l]);
            a0 += f0.x; a1 += f0.y;
        }
    }
    unsigned v = pk2(s * a0, s * a1);
    reinterpret_cast<unsigned*>(g_aggb)[(size_t)n * 32 + l] = v;  // full 64-col layout
}

// ---------------- fused: stage-t + HMMA (4x2 warp grid, x4 B loads) + epilogue ----------------
#define SMEM_A_OFF   0
#define SMEM_BH_OFF  16384
#define SMEM_BS_OFF  32768
#define SMEM_PL_OFF  33024
#define SMEM_TOTAL   34048

__device__ __forceinline__ void stage8(uint4 H, uint4 A, uint4 B, float dv, unsigned* o) {
    float hh[8], a0[8], a1[8];
    upk8(H, hh); upk8(A, a0); upk8(B, a1);
    #pragma unroll
    for (int j = 0; j < 4; j++)
        o[j] = pk2(dv * (hh[2 * j] + a0[2 * j] + a1[2 * j]),
                   dv * (hh[2 * j + 1] + a0[2 * j + 1] + a1[2 * j + 1]));
}

template <int LAYER, bool WRITE_H>
__global__ __launch_bounds__(256) void fused_kernel(const float* __restrict__ bias,
                                                    const float* __restrict__ ea,
                                                    float* __restrict__ out) {
    extern __shared__ char smem[];
    uint32_t sb = smem_to_u32(smem);
    float* spool = reinterpret_cast<float*>(smem + SMEM_PL_OFF);  // [8 warps][32 cols]
    int tid = threadIdx.x, wid = tid >> 5, lane = tid & 31;
    int e0 = blockIdx.x * 128;

    {   // W (hi+lo 16KB, pre-swizzled)
        const uint4* src = reinterpret_cast<const uint4*>(&g_Wb[LAYER - 1][0][0]);
        uint4* dst = reinterpret_cast<uint4*>(smem + SMEM_BH_OFF);
        #pragma unroll
        for (int i = 0; i < 4; i++) dst[tid + 256 * i] = src[tid + 256 * i];
    }
    if (tid < 64) reinterpret_cast<float*>(smem + SMEM_BS_OFF)[tid] = bias[tid];

    // ---- stage t tile (128 rows x K bf16, swizzled 128B rows) ----
    if (LAYER == 1) {
        int r = tid >> 1, hf = tid & 1, c0 = hf * 16;
        long long e = e0 + r;
        float v[16];
        if (e < NE) {
            int2 nn = g_ei01p[e];
            int og = g_eorig[e];
            float dv = g_dinvp[e], im = g_impp[e];
            const float4* pa = reinterpret_cast<const float4*>(ea + (size_t)og * 32 + c0);
            const uint4* q0 = reinterpret_cast<const uint4*>(g_aggb + (size_t)nn.x * 32 + c0);
            const uint4* q1 = reinterpret_cast<const uint4*>(g_aggb + (size_t)nn.y * 32 + c0);
            float a0[16], a1[16];
            upk8(q0[0], a0); upk8(q0[1], a0 + 8);
            upk8(q1[0], a1); upk8(q1[1], a1 + 8);
            #pragma unroll
            for (int q = 0; q < 4; q++) {
                float4 a = pa[q];
                v[q * 4 + 0] = dv * (im * a.x + a0[q * 4 + 0] + a1[q * 4 + 0]);
                v[q * 4 + 1] = dv * (im * a.y + a0[q * 4 + 1] + a1[q * 4 + 1]);
                v[q * 4 + 2] = dv * (im * a.z + a0[q * 4 + 2] + a1[q * 4 + 2]);
                v[q * 4 + 3] = dv * (im * a.w + a0[q * 4 + 3] + a1[q * 4 + 3]);
            }
        } else {
            #pragma unroll
            for (int q = 0; q < 16; q++) v[q] = 0.f;
        }
        unsigned off = (unsigned)(r * 128 + c0 * 2);
        *reinterpret_cast<uint4*>(smem + SMEM_A_OFF + sw128(off)) =
            make_uint4(pk2(v[0], v[1]), pk2(v[2], v[3]), pk2(v[4], v[5]), pk2(v[6], v[7]));
        *reinterpret_cast<uint4*>(smem + SMEM_A_OFF + sw128(off + 16)) =
            make_uint4(pk2(v[8], v[9]), pk2(v[10], v[11]), pk2(v[12], v[13]), pk2(v[14], v[15]));
        // no zero padding: layer-1 MMA (KSTEPS=2) never reads bytes 64..127
    } else {
        #pragma unroll
        for (int pass = 0; pass < 2; pass++) {
            int r = (tid >> 2) + pass * 64;
            int q = tid & 3, c0 = q * 16;
            long long e = e0 + r;
            unsigned o0[4], o1[4];
            if (e < NE) {
                int2 nn = g_ei01p[e];
                float dv = g_dinvp[e];
                const uint4* ph = reinterpret_cast<const uint4*>(g_hb + (size_t)e * 64 + c0);
                const uint4* q0 = reinterpret_cast<const uint4*>(g_aggb + (size_t)nn.x * 64 + c0);
                const uint4* q1 = reinterpret_cast<const uint4*>(g_aggb + (size_t)nn.y * 64 + c0);
                uint4 H0 = ph[0], H1 = ph[1];
                uint4 A0 = q0[0], A1 = q0[1];
                uint4 B0 = q1[0], B1 = q1[1];
                stage8(H0, A0, B0, dv, o0);
                stage8(H1, A1, B1, dv, o1);
            } else {
                #pragma unroll
                for (int j = 0; j < 4; j++) { o0[j] = 0u; o1[j] = 0u; }
            }
            unsigned off = (unsigned)(r * 128 + c0 * 2);
            *reinterpret_cast<uint4*>(smem + SMEM_A_OFF + sw128(off)) =
                make_uint4(o0[0], o0[1], o0[2], o0[3]);
            *reinterpret_cast<uint4*>(smem + SMEM_A_OFF + sw128(off + 16)) =
                make_uint4(o1[0], o1[1], o1[2], o1[3]);
        }
    }
    __syncthreads();

    // ---- warp-level HMMA: 4x2 warp grid; B fragments via x4 (2 n-tiles/ldsm) ----
    constexpr int KSTEPS = (LAYER == 1) ? 2 : 4;
    int wr = wid & 3, wc = wid >> 2;
    float acc[2][4][4];
    #pragma unroll
    for (int m = 0; m < 2; m++)
        #pragma unroll
        for (int nt = 0; nt < 4; nt++) {
            acc[m][nt][0] = 0.f; acc[m][nt][1] = 0.f;
            acc[m][nt][2] = 0.f; acc[m][nt][3] = 0.f;
        }
    unsigned acol = (unsigned)(lane >> 4) * 16;
    unsigned alr  = (unsigned)(lane & 15);
    unsigned bsel = (unsigned)((lane >> 3) & 1) * 16;   // k-half within n-tile
    unsigned bnt  = (unsigned)(lane >> 4);              // which n-tile of the pair
    unsigned blr  = (unsigned)(lane & 7);

    #pragma unroll
    for (int kk = 0; kk < KSTEPS; kk++) {
        unsigned kb = (unsigned)kk * 32;
        uint32_t a[2][4];
        #pragma unroll
        for (int m = 0; m < 2; m++) {
            unsigned arow = (unsigned)(wr * 32 + m * 16) + alr;
            ldsm_x4(a[m][0], a[m][1], a[m][2], a[m][3],
                    sb + SMEM_A_OFF + sw128(arow * 128 + acol + kb));
        }
        #pragma unroll
        for (int pass = 0; pass < 2; pass++) {
            uint32_t wb = sb + SMEM_BH_OFF + (unsigned)pass * 8192u;
            #pragma unroll
            for (int np = 0; np < 2; np++) {   // n-tile pairs (0,1) and (2,3)
                unsigned brow = (unsigned)(wc * 32) + (np * 2u + bnt) * 8u + blr;
                uint32_t b0, b1, b2, b3;
                ldsm_x4(b0, b1, b2, b3, wb + sw128(brow * 128 + kb + bsel));
                mma16816(acc[0][np * 2],     a[0][0], a[0][1], a[0][2], a[0][3], b0, b1);
                mma16816(acc[1][np * 2],     a[1][0], a[1][1], a[1][2], a[1][3], b0, b1);
                mma16816(acc[0][np * 2 + 1], a[0][0], a[0][1], a[0][2], a[0][3], b2, b3);
                mma16816(acc[1][np * 2 + 1], a[1][0], a[1][1], a[1][2], a[1][3], b2, b3);
            }
        }
    }

    // ---- epilogue: bias + relu + imp; shfl-based pool; optional bf16 writeback ----
    const int LOFF = (LAYER - 1) * 64;
    {
        int g = lane >> 2, q = lane & 3;
        int gA = g_ebp[e0];
        long long elast = (long long)e0 + 127 < NE ? (long long)e0 + 127 : NE - 1;
        bool uni = (g_ebp[elast] == gA);       // block entirely within one graph
        const float* sB = reinterpret_cast<const float*>(smem + SMEM_BS_OFF);
        float pacc[4][2];
        #pragma unroll
        for (int nt = 0; nt < 4; nt++) { pacc[nt][0] = 0.f; pacc[nt][1] = 0.f; }
        #pragma unroll
        for (int m = 0; m < 2; m++) {
            long long ra = e0 + wr * 32 + m * 16 + g, rb = ra + 8;
            bool oka = ra < NE, okb = rb < NE;
            float ia = oka ? g_impp[ra] : 0.f;
            float ib = okb ? g_impp[rb] : 0.f;
            int ga = oka ? g_ebp[ra] : gA;
            int gb = okb ? g_ebp[rb] : gA;
            #pragma unroll
            for (int nt = 0; nt < 4; nt++) {
                int c0 = wc * 32 + nt * 8 + q * 2;
                float bz0 = sB[c0], bz1 = sB[c0 + 1];
                float va0 = fmaxf(acc[m][nt][0] + bz0, 0.f) * ia;
                float va1 = fmaxf(acc[m][nt][1] + bz1, 0.f) * ia;
                float vb0 = fmaxf(acc[m][nt][2] + bz0, 0.f) * ib;
                float vb1 = fmaxf(acc[m][nt][3] + bz1, 0.f) * ib;
                pacc[nt][0] += va0 + vb0;
                pacc[nt][1] += va1 + vb1;
                if (!uni) {   // rare: block straddles a graph boundary
                    if (oka) { atomicAdd(&out[ga * 192 + LOFF + c0], va0);
                               atomicAdd(&out[ga * 192 + LOFF + c0 + 1], va1); }
                    if (okb) { atomicAdd(&out[gb * 192 + LOFF + c0], vb0);
                               atomicAdd(&out[gb * 192 + LOFF + c0 + 1], vb1); }
                }
                if (WRITE_H) {
                    int rrow = wr * 32 + m * 16 + g;
                    *reinterpret_cast<unsigned*>(smem + sw128((unsigned)(rrow * 128 + c0 * 2))) =
                        pk2(va0, va1);
                    *reinterpret_cast<unsigned*>(smem + sw128((unsigned)((rrow + 8) * 128 + c0 * 2))) =
                        pk2(vb0, vb1);
                }
            }
        }
        if (uni) {
            #pragma unroll
            for (int o = 4; o < 32; o <<= 1) {
                #pragma unroll
                for (int nt = 0; nt < 4; nt++) {
                    pacc[nt][0] += __shfl_xor_sync(0xffffffffu, pacc[nt][0], o);
                    pacc[nt][1] += __shfl_xor_sync(0xffffffffu, pacc[nt][1], o);
                }
            }
            if (g == 0) {   // lanes 0..3 hold warp column sums (32 cols per warp)
                #pragma unroll
                for (int nt = 0; nt < 4; nt++) {
                    spool[wid * 32 + nt * 8 + q * 2]     = pacc[nt][0];
                    spool[wid * 32 + nt * 8 + q * 2 + 1] = pacc[nt][1];
                }
            }
        }
        __syncthreads();
        if (uni && tid < 64) {
            int c = tid & 31, wcn = tid >> 5;
            float s = 0.f;
            #pragma unroll
            for (int j = 0; j < 4; j++) s += spool[(wcn * 4 + j) * 32 + c];
            atomicAdd(&out[gA * 192 + LOFF + wcn * 32 + c], s);
        }
    }

    if (WRITE_H) {
        int r = tid >> 1, hf = tid & 1;
        long long e = e0 + r;
        if (e < NE) {
            uint4 x0 = *reinterpret_cast<const uint4*>(smem + sw128((unsigned)(r * 128 + hf * 64)));
            uint4 x1 = *reinterpret_cast<const uint4*>(smem + sw128((unsigned)(r * 128 + hf * 64 + 16)));
            uint4 x2 = *reinterpret_cast<const uint4*>(smem + sw128((unsigned)(r * 128 + hf * 64 + 32)));
            uint4 x3 = *reinterpret_cast<const uint4*>(smem + sw128((unsigned)(r * 128 + hf * 64 + 48)));
            uint4* dst = reinterpret_cast<uint4*>(g_hb + (size_t)e * 64 + hf * 32);
            dst[0] = x0; dst[1] = x1; dst[2] = x2; dst[3] = x3;
        }
    }
}

// ---------------- tail: reset counters for next replay ----------------
__global__ void cleanup_kernel() {
    int i = blockIdx.x * 256 + threadIdx.x;
    if (i < NN) { g_deg[i] = 0; g_cursor[i] = 0; }
    if (i < NGR) { g_gcnt[i] = 0; g_gcur[i] = 0; g_flag[i] = 0; }
    if (i == 0) g_done = 0;
}

// ---------------- launch ----------------
extern "C" void kernel_launch(void* const* d_in, const int* in_sizes, int n_in,
                              void* d_out, int out_size) {
    const float* edge_attr = (const float*)d_in[1];
    const int*   eidx      = (const int*)d_in[2];
    const int*   batch     = (const int*)d_in[3];
    const float* nimp      = (const float*)d_in[4];
    const float* W0 = (const float*)d_in[5];
    const float* b0 = (const float*)d_in[6];
    const float* W1 = (const float*)d_in[7];
    const float* b1 = (const float*)d_in[8];
    const float* W2 = (const float*)d_in[9];
    const float* b2 = (const float*)d_in[10];
    float* out = (float*)d_out;

    const int AGG_BLKS = (NN + 7) / 8;

    deg_all<<<EDGE_BLKS + 48 + 3, 256>>>(out, eidx, batch, W0, W1, W2);   // #1
    scanedge_kernel<<<49, 1024>>>(eidx, batch, nimp);                     // #2
    agg1_kernel<<<AGG_BLKS, 256>>>(edge_attr);                            // #3
    fused_kernel<1, true><<<FUS_BLOCKS, 256, SMEM_TOTAL>>>(b0, edge_attr, out);  // #4 <- ncu
    agg64_kernel<<<AGG_BLKS, 256>>>();
    fused_kernel<2, true><<<FUS_BLOCKS, 256, SMEM_TOTAL>>>(b1, nullptr, out);
    agg64_kernel<<<AGG_BLKS, 256>>>();
    fused_kernel<3, false><<<FUS_BLOCKS, 256, SMEM_TOTAL>>>(b2, nullptr, out);
    cleanup_kernel<<<196, 256>>>();
}

// round 16
// speedup vs baseline: 1.0846x; 1.0304x over previous
#include <cuda_runtime.h>
#include <cuda_fp16.h>
#include <cstdint>

#define NN   50000
#define NE   500000
#define NGR  64
#define FUS_BLOCKS ((NE + 127) / 128)
#define EDGE_BLKS ((NE + 255) / 256)

// ---------------- device scratch (zero-initialized at load; cleanup re-zeros) ----------------
__device__ __align__(16) __half g_hb[(size_t)NE * 64];    // 64 MB, in-place
__device__ __align__(16) __half g_aggb[(size_t)NN * 64];  // 6.4 MB fp16 node agg
__device__ int   g_deg[NN];
__device__ int   g_cursor[NN];
__device__ float g_s[NN];
__device__ int   g_csr_off[NN + 1];
__device__ int   g_csr_edges[2 * NE];           // pe (for agg64)
__device__ __align__(8) int2 g_csr_oi[2 * NE];  // {orig_edge, imp bits} (for agg1)
__device__ __align__(8) int2 g_ei01p[NE];       // {n0, n1}
__device__ int   g_gcnt[NGR];
__device__ int   g_gcur[NGR];
__device__ int   g_gstart[NGR + 1];
__device__ int   g_eorig[NE];
__device__ int   g_ebp[NE];
__device__ float g_impp[NE];
__device__ float g_dinvp[NE];
__device__ __align__(16) unsigned char g_Wh[3][8192];  // swizzled fp16 W
__device__ int   g_is64;
__device__ volatile int g_flag[64];
__device__ volatile int g_pref[64];
__device__ int   g_done;

// ---------------- helpers ----------------
__device__ __forceinline__ uint32_t smem_to_u32(const void* p) {
    uint32_t a;
    asm("{ .reg .u64 t; cvta.to.shared.u64 t, %1; cvt.u32.u64 %0, t; }" : "=r"(a) : "l"(p));
    return a;
}
__device__ __forceinline__ unsigned pk2(float a, float b) {
    __half2 t = __floats2half2_rn(a, b);
    return reinterpret_cast<unsigned&>(t);
}
__device__ __forceinline__ void upk8(uint4 u, float* d) {
    unsigned w[4] = {u.x, u.y, u.z, u.w};
    #pragma unroll
    for (int i = 0; i < 4; i++) {
        unsigned ww = w[i];
        __half2 t = reinterpret_cast<__half2&>(ww);
        float2 f = __half22float2(t);
        d[2 * i] = f.x; d[2 * i + 1] = f.y;
    }
}
__device__ __forceinline__ unsigned sw128(unsigned off) { return off ^ ((off >> 3) & 0x70); }

__device__ __forceinline__ int LD_IDX(const int* __restrict__ p, long long i) {
    return g_is64 ? p[2 * i] : p[(size_t)i];
}

__device__ __forceinline__ void ldsm_x4(uint32_t& a0, uint32_t& a1, uint32_t& a2, uint32_t& a3,
                                        uint32_t addr) {
    asm volatile("ldmatrix.sync.aligned.m8n8.x4.shared.b16 {%0,%1,%2,%3}, [%4];"
                 : "=r"(a0), "=r"(a1), "=r"(a2), "=r"(a3) : "r"(addr));
}
__device__ __forceinline__ void mma16816(float* c, uint32_t a0, uint32_t a1, uint32_t a2,
                                         uint32_t a3, uint32_t b0, uint32_t b1) {
    asm volatile("mma.sync.aligned.m16n8k16.row.col.f32.f16.f16.f32 "
                 "{%0,%1,%2,%3}, {%4,%5,%6,%7}, {%8,%9}, {%0,%1,%2,%3};"
                 : "+f"(c[0]), "+f"(c[1]), "+f"(c[2]), "+f"(c[3])
                 : "r"(a0), "r"(a1), "r"(a2), "r"(a3), "r"(b0), "r"(b1));
}

// ---------------- K1: deg + gcnt + out-zero + detect + wprep ----------------
__global__ __launch_bounds__(256) void deg_all(float* __restrict__ out,
                                               const int* __restrict__ eidx,
                                               const int* __restrict__ batch,
                                               const float* __restrict__ W0,
                                               const float* __restrict__ W1,
                                               const float* __restrict__ W2) {
    int b = blockIdx.x, tid = threadIdx.x;
    if (b < EDGE_BLKS) {
        __shared__ int sh[NGR];
        __shared__ int s_is64;
        if (tid < NGR) sh[tid] = 0;
        if (tid == 0) {
            int z = 0;
            #pragma unroll
            for (int i = 0; i < 64; i++) z |= eidx[2 * i + 1];
            s_is64 = (z == 0) ? 1 : 0;
            if (b == 0) g_is64 = s_is64;
        }
        __syncthreads();
        int is64 = s_is64;
        int e = b * 256 + tid;
        if (e < NE) {
            int a = is64 ? eidx[2 * e] : eidx[e];
            int c = is64 ? eidx[2 * ((long long)NE + e)] : eidx[NE + e];
            atomicAdd(&g_deg[a], 1);
            atomicAdd(&g_deg[c], 1);
            int g = is64 ? batch[2 * a] : batch[a];
            atomicAdd(&sh[g], 1);
        }
        __syncthreads();
        if (tid < NGR && sh[tid] > 0) atomicAdd(&g_gcnt[tid], sh[tid]);
    } else if (b < EDGE_BLKS + 48) {
        int i = (b - EDGE_BLKS) * 256 + tid;
        if (i < NGR * 192) out[i] = 0.f;
    } else {
        int l = b - (EDGE_BLKS + 48);
        const float* W = (l == 0) ? W0 : ((l == 1) ? W1 : W2);
        int KIN = (l == 0) ? 32 : 64;
        for (int i = tid; i < 4096; i += 256) {
            int n = i >> 6, k = i & 63;
            float w = (k < KIN) ? W[k * 64 + n] : 0.f;
            unsigned sw = sw128((unsigned)(n * 128 + k * 2));
            *reinterpret_cast<__half*>(&g_Wh[l][sw]) = __float2half_rn(w);
        }
    }
}

// ---------------- K2: scan (decoupled lookback) + node + gstart + edge pass ----------------
__global__ __launch_bounds__(1024) void scanedge_kernel(const int* __restrict__ eidx,
                                                        const int* __restrict__ batch,
                                                        const float* __restrict__ nimp) {
    __shared__ int ws[32];
    __shared__ int wo[32];
    __shared__ int s_total;
    __shared__ int s_pref;
    int tid = threadIdx.x, lane = tid & 31, w = tid >> 5;
    int bid = blockIdx.x;
    int i = bid * 1024 + tid;
    int v = (i < NN) ? g_deg[i] : 0;
    int inc = v;
    #pragma unroll
    for (int o = 1; o < 32; o <<= 1) {
        int u = __shfl_up_sync(0xffffffffu, inc, o);
        if (lane >= o) inc += u;
    }
    if (lane == 31) ws[w] = inc;
    __syncthreads();
    if (w == 0) {
        int x = ws[lane], xi = x;
        #pragma unroll
        for (int o = 1; o < 32; o <<= 1) {
            int u = __shfl_up_sync(0xffffffffu, xi, o);
            if (lane >= o) xi += u;
        }
        wo[lane] = xi - x;
        if (lane == 31) s_total = xi;
    }
    __syncthreads();
    if (tid == 0) {
        int p = 0;
        if (bid > 0) {
            while (g_flag[bid - 1] == 0) { }
            p = g_pref[bid - 1];
        }
        g_pref[bid] = p + s_total;
        __threadfence();
        g_flag[bid] = 1;
        s_pref = p;
    }
    __syncthreads();
    if (i < NN) {
        g_csr_off[i] = s_pref + wo[w] + inc - v;
        g_s[i] = (v > 1) ? 1.0f / (float)v : 0.0f;
    }
    if (bid == 48 && tid == 0) {
        while (g_flag[48] == 0) { }
        g_csr_off[NN] = g_pref[48];
        int r2 = 0;
        for (int g = 0; g < NGR; g++) { g_gstart[g] = r2; r2 += g_gcnt[g]; }
        g_gstart[NGR] = r2;
    }
    __syncthreads();
    if (tid == 0) {
        __threadfence();
        atomicAdd(&g_done, 1);
        while (*(volatile int*)&g_done < 49) { }
    }
    __syncthreads();
    // ---- edge pass (grid-stride over 49x1024 threads) ----
    for (long long e = bid * 1024 + tid; e < NE; e += 49 * 1024) {
        int a = LD_IDX(eidx, e);
        int b = LD_IDX(eidx, (long long)NE + e);
        int g = LD_IDX(batch, a);
        int pe = g_gstart[g] + atomicAdd(&g_gcur[g], 1);
        float im = fminf(nimp[a], nimp[b]);
        g_ei01p[pe] = make_int2(a, b);
        g_eorig[pe] = (int)e;
        g_ebp[pe]   = g;
        g_impp[pe]  = im;
        int ka = (g_deg[a] != 1) ? 1 : 0;
        int kb = (g_deg[b] != 1) ? 1 : 0;
        g_dinvp[pe] = 1.0f / (float)(1 + ka + kb);
        int2 oi = make_int2((int)e, __float_as_int(im));
        int p = atomicAdd(&g_cursor[a], 1);
        int sa = g_csr_off[a] + p;
        g_csr_edges[sa] = pe;
        g_csr_oi[sa] = oi;
        p = atomicAdd(&g_cursor[b], 1);
        int sb2 = g_csr_off[b] + p;
        g_csr_edges[sb2] = pe;
        g_csr_oi[sb2] = oi;
    }
}

// ---------------- K3: agg1 (2-level chain via packed csr_oi) ----------------
__global__ __launch_bounds__(256) void agg1_kernel(const float* __restrict__ ea) {
    int n = blockIdx.x * 8 + (threadIdx.x >> 5);
    if (n >= NN) return;
    int l = threadIdx.x & 31;
    float s = g_s[n];
    float acc = 0.f;
    if (s != 0.f) {
        int i = g_csr_off[n], e = g_csr_off[n + 1];
        for (; i + 8 <= e; i += 8) {
            float x[8];
            #pragma unroll
            for (int j = 0; j < 8; j++) {
                int2 oi = g_csr_oi[i + j];
                x[j] = __int_as_float(oi.y) * ea[(size_t)oi.x * 32 + l];
            }
            acc += ((x[0] + x[1]) + (x[2] + x[3])) + ((x[4] + x[5]) + (x[6] + x[7]));
        }
        for (; i < e; i++) {
            int2 oi = g_csr_oi[i];
            acc += __int_as_float(oi.y) * ea[(size_t)oi.x * 32 + l];
        }
    }
    g_aggb[(size_t)n * 32 + l] = __float2half_rn(s * acc);   // compact 32-col layout
}

__global__ __launch_bounds__(256) void agg64_kernel() {
    const __half* __restrict__ hb = g_hb;
    int n = blockIdx.x * 8 + (threadIdx.x >> 5);
    if (n >= NN) return;
    int l = threadIdx.x & 31;
    float s = g_s[n];
    float a0 = 0.f, a1 = 0.f;
    if (s != 0.f) {
        int i = g_csr_off[n], e = g_csr_off[n + 1];
        for (; i + 8 <= e; i += 8) {
            float2 f[8];
            #pragma unroll
            for (int j = 0; j < 8; j++) {
                int p = g_csr_edges[i + j];
                f[j] = __half22float2(
                    reinterpret_cast<const __half2*>(hb + (size_t)p * 64)[l]);
            }
            a0 += ((f[0].x + f[1].x) + (f[2].x + f[3].x)) + ((f[4].x + f[5].x) + (f[6].x + f[7].x));
            a1 += ((f[0].y + f[1].y) + (f[2].y + f[3].y)) + ((f[4].y + f[5].y) + (f[6].y + f[7].y));
        }
        for (; i < e; i++) {
            int p = g_csr_edges[i];
            float2 f0 = __half22float2(
                reinterpret_cast<const __half2*>(hb + (size_t)p * 64)[l]);
            a0 += f0.x; a1 += f0.y;
        }
    }
    unsigned v = pk2(s * a0, s * a1);
    reinterpret_cast<unsigned*>(g_aggb)[(size_t)n * 32 + l] = v;  // full 64-col layout
}

// ---------------- fused: stage-t(fp16) + HMMA (4x2 warps, single W pass) + epilogue ----------------
#define SMEM_A_OFF   0
#define SMEM_BH_OFF  16384
#define SMEM_BS_OFF  24576
#define SMEM_PL_OFF  24832
#define SMEM_TOTAL   25856

__device__ __forceinline__ void stage8(uint4 H, uint4 A, uint4 B, float dv, unsigned* o) {
    float hh[8], a0[8], a1[8];
    upk8(H, hh); upk8(A, a0); upk8(B, a1);
    #pragma unroll
    for (int j = 0; j < 4; j++)
        o[j] = pk2(dv * (hh[2 * j] + a0[2 * j] + a1[2 * j]),
                   dv * (hh[2 * j + 1] + a0[2 * j + 1] + a1[2 * j + 1]));
}

template <int LAYER, bool WRITE_H>
__global__ __launch_bounds__(256) void fused_kernel(const float* __restrict__ bias,
                                                    const float* __restrict__ ea,
                                                    float* __restrict__ out) {
    extern __shared__ char smem[];
    uint32_t sb = smem_to_u32(smem);
    float* spool = reinterpret_cast<float*>(smem + SMEM_PL_OFF);  // [8 warps][32 cols]
    int tid = threadIdx.x, wid = tid >> 5, lane = tid & 31;
    int e0 = blockIdx.x * 128;

    {   // W (8KB fp16, pre-swizzled)
        const uint4* src = reinterpret_cast<const uint4*>(&g_Wh[LAYER - 1][0]);
        uint4* dst = reinterpret_cast<uint4*>(smem + SMEM_BH_OFF);
        #pragma unroll
        for (int i = 0; i < 2; i++) dst[tid + 256 * i] = src[tid + 256 * i];
    }
    if (tid < 64) reinterpret_cast<float*>(smem + SMEM_BS_OFF)[tid] = bias[tid];

    // ---- stage t tile (128 rows x K fp16, swizzled 128B rows) ----
    if (LAYER == 1) {
        int r = tid >> 1, hf = tid & 1, c0 = hf * 16;
        long long e = e0 + r;
        float v[16];
        if (e < NE) {
            int2 nn = g_ei01p[e];
            int og = g_eorig[e];
            float dv = g_dinvp[e], im = g_impp[e];
            const float4* pa = reinterpret_cast<const float4*>(ea + (size_t)og * 32 + c0);
            const uint4* q0 = reinterpret_cast<const uint4*>(g_aggb + (size_t)nn.x * 32 + c0);
            const uint4* q1 = reinterpret_cast<const uint4*>(g_aggb + (size_t)nn.y * 32 + c0);
            float a0[16], a1[16];
            upk8(q0[0], a0); upk8(q0[1], a0 + 8);
            upk8(q1[0], a1); upk8(q1[1], a1 + 8);
            #pragma unroll
            for (int q = 0; q < 4; q++) {
                float4 a = pa[q];
                v[q * 4 + 0] = dv * (im * a.x + a0[q * 4 + 0] + a1[q * 4 + 0]);
                v[q * 4 + 1] = dv * (im * a.y + a0[q * 4 + 1] + a1[q * 4 + 1]);
                v[q * 4 + 2] = dv * (im * a.z + a0[q * 4 + 2] + a1[q * 4 + 2]);
                v[q * 4 + 3] = dv * (im * a.w + a0[q * 4 + 3] + a1[q * 4 + 3]);
            }
        } else {
            #pragma unroll
            for (int q = 0; q < 16; q++) v[q] = 0.f;
        }
        unsigned off = (unsigned)(r * 128 + c0 * 2);
        *reinterpret_cast<uint4*>(smem + SMEM_A_OFF + sw128(off)) =
            make_uint4(pk2(v[0], v[1]), pk2(v[2], v[3]), pk2(v[4], v[5]), pk2(v[6], v[7]));
        *reinterpret_cast<uint4*>(smem + SMEM_A_OFF + sw128(off + 16)) =
            make_uint4(pk2(v[8], v[9]), pk2(v[10], v[11]), pk2(v[12], v[13]), pk2(v[14], v[15]));
        // no zero padding: layer-1 MMA (KSTEPS=2) never reads bytes 64..127
    } else {
        #pragma unroll
        for (int pass = 0; pass < 2; pass++) {
            int r = (tid >> 2) + pass * 64;
            int q = tid & 3, c0 = q * 16;
            long long e = e0 + r;
            unsigned o0[4], o1[4];
            if (e < NE) {
                int2 nn = g_ei01p[e];
                float dv = g_dinvp[e];
                const uint4* ph = reinterpret_cast<const uint4*>(g_hb + (size_t)e * 64 + c0);
                const uint4* q0 = reinterpret_cast<const uint4*>(g_aggb + (size_t)nn.x * 64 + c0);
                const uint4* q1 = reinterpret_cast<const uint4*>(g_aggb + (size_t)nn.y * 64 + c0);
                uint4 H0 = ph[0], H1 = ph[1];
                uint4 A0 = q0[0], A1 = q0[1];
                uint4 B0 = q1[0], B1 = q1[1];
                stage8(H0, A0, B0, dv, o0);
                stage8(H1, A1, B1, dv, o1);
            } else {
                #pragma unroll
                for (int j = 0; j < 4; j++) { o0[j] = 0u; o1[j] = 0u; }
            }
            unsigned off = (unsigned)(r * 128 + c0 * 2);
            *reinterpret_cast<uint4*>(smem + SMEM_A_OFF + sw128(off)) =
                make_uint4(o0[0], o0[1], o0[2], o0[3]);
            *reinterpret_cast<uint4*>(smem + SMEM_A_OFF + sw128(off + 16)) =
                make_uint4(o1[0], o1[1], o1[2], o1[3]);
        }
    }
    __syncthreads();

    // ---- warp-level HMMA: 4x2 warp grid; single fp16 W pass; x4 B loads ----
    constexpr int KSTEPS = (LAYER == 1) ? 2 : 4;
    int wr = wid & 3, wc = wid >> 2;
    float acc[2][4][4];
    #pragma unroll
    for (int m = 0; m < 2; m++)
        #pragma unroll
        for (int nt = 0; nt < 4; nt++) {
            acc[m][nt][0] = 0.f; acc[m][nt][1] = 0.f;
            acc[m][nt][2] = 0.f; acc[m][nt][3] = 0.f;
        }
    unsigned acol = (unsigned)(lane >> 4) * 16;
    unsigned alr  = (unsigned)(lane & 15);
    unsigned bsel = (unsigned)((lane >> 3) & 1) * 16;   // k-half within n-tile
    unsigned bnt  = (unsigned)(lane >> 4);              // which n-tile of the pair
    unsigned blr  = (unsigned)(lane & 7);

    #pragma unroll
    for (int kk = 0; kk < KSTEPS; kk++) {
        unsigned kb = (unsigned)kk * 32;
        uint32_t a[2][4];
        #pragma unroll
        for (int m = 0; m < 2; m++) {
            unsigned arow = (unsigned)(wr * 32 + m * 16) + alr;
            ldsm_x4(a[m][0], a[m][1], a[m][2], a[m][3],
                    sb + SMEM_A_OFF + sw128(arow * 128 + acol + kb));
        }
        uint32_t wb = sb + SMEM_BH_OFF;
        #pragma unroll
        for (int np = 0; np < 2; np++) {   // n-tile pairs (0,1) and (2,3)
            unsigned brow = (unsigned)(wc * 32) + (np * 2u + bnt) * 8u + blr;
            uint32_t b0, b1, b2, b3;
            ldsm_x4(b0, b1, b2, b3, wb + sw128(brow * 128 + kb + bsel));
            mma16816(acc[0][np * 2],     a[0][0], a[0][1], a[0][2], a[0][3], b0, b1);
            mma16816(acc[1][np * 2],     a[1][0], a[1][1], a[1][2], a[1][3], b0, b1);
            mma16816(acc[0][np * 2 + 1], a[0][0], a[0][1], a[0][2], a[0][3], b2, b3);
            mma16816(acc[1][np * 2 + 1], a[1][0], a[1][1], a[1][2], a[1][3], b2, b3);
        }
    }

    // ---- epilogue: bias + relu + imp; shfl-based pool; optional fp16 writeback ----
    const int LOFF = (LAYER - 1) * 64;
    {
        int g = lane >> 2, q = lane & 3;
        int gA = g_ebp[e0];
        long long elast = (long long)e0 + 127 < NE ? (long long)e0 + 127 : NE - 1;
        bool uni = (g_ebp[elast] == gA);       // block entirely within one graph
        const float* sB = reinterpret_cast<const float*>(smem + SMEM_BS_OFF);
        float pacc[4][2];
        #pragma unroll
        for (int nt = 0; nt < 4; nt++) { pacc[nt][0] = 0.f; pacc[nt][1] = 0.f; }
        #pragma unroll
        for (int m = 0; m < 2; m++) {
            long long ra = e0 + wr * 32 + m * 16 + g, rb = ra + 8;
            bool oka = ra < NE, okb = rb < NE;
            float ia = oka ? g_impp[ra] : 0.f;
            float ib = okb ? g_impp[rb] : 0.f;
            int ga = oka ? g_ebp[ra] : gA;
            int gb = okb ? g_ebp[rb] : gA;
            #pragma unroll
            for (int nt = 0; nt < 4; nt++) {
                int c0 = wc * 32 + nt * 8 + q * 2;
                float bz0 = sB[c0], bz1 = sB[c0 + 1];
                float va0 = fmaxf(acc[m][nt][0] + bz0, 0.f) * ia;
                float va1 = fmaxf(acc[m][nt][1] + bz1, 0.f) * ia;
                float vb0 = fmaxf(acc[m][nt][2] + bz0, 0.f) * ib;
                float vb1 = fmaxf(acc[m][nt][3] + bz1, 0.f) * ib;
                pacc[nt][0] += va0 + vb0;
                pacc[nt][1] += va1 + vb1;
                if (!uni) {   // rare: block straddles a graph boundary
                    if (oka) { atomicAdd(&out[ga * 192 + LOFF + c0], va0);
                               atomicAdd(&out[ga * 192 + LOFF + c0 + 1], va1); }
                    if (okb) { atomicAdd(&out[gb * 192 + LOFF + c0], vb0);
                               atomicAdd(&out[gb * 192 + LOFF + c0 + 1], vb1); }
                }
                if (WRITE_H) {
                    int rrow = wr * 32 + m * 16 + g;
                    *reinterpret_cast<unsigned*>(smem + sw128((unsigned)(rrow * 128 + c0 * 2))) =
                        pk2(va0, va1);
                    *reinterpret_cast<unsigned*>(smem + sw128((unsigned)((rrow + 8) * 128 + c0 * 2))) =
                        pk2(vb0, vb1);
                }
            }
        }
        if (uni) {
            #pragma unroll
            for (int o = 4; o < 32; o <<= 1) {
                #pragma unroll
                for (int nt = 0; nt < 4; nt++) {
                    pacc[nt][0] += __shfl_xor_sync(0xffffffffu, pacc[nt][0], o);
                    pacc[nt][1] += __shfl_xor_sync(0xffffffffu, pacc[nt][1], o);
                }
            }
            if (g == 0) {   // lanes 0..3 hold warp column sums (32 cols per warp)
                #pragma unroll
                for (int nt = 0; nt < 4; nt++) {
                    spool[wid * 32 + nt * 8 + q * 2]     = pacc[nt][0];
                    spool[wid * 32 + nt * 8 + q * 2 + 1] = pacc[nt][1];
                }
            }
        }
        __syncthreads();
        if (uni && tid < 64) {
            int c = tid & 31, wcn = tid >> 5;
            float s = 0.f;
            #pragma unroll
            for (int j = 0; j < 4; j++) s += spool[(wcn * 4 + j) * 32 + c];
            atomicAdd(&out[gA * 192 + LOFF + wcn * 32 + c], s);
        }
    }

    if (WRITE_H) {
        int r = tid >> 1, hf = tid & 1;
        long long e = e0 + r;
        if (e < NE) {
            uint4 x0 = *reinterpret_cast<const uint4*>(smem + sw128((unsigned)(r * 128 + hf * 64)));
            uint4 x1 = *reinterpret_cast<const uint4*>(smem + sw128((unsigned)(r * 128 + hf * 64 + 16)));
            uint4 x2 = *reinterpret_cast<const uint4*>(smem + sw128((unsigned)(r * 128 + hf * 64 + 32)));
            uint4 x3 = *reinterpret_cast<const uint4*>(smem + sw128((unsigned)(r * 128 + hf * 64 + 48)));
            uint4* dst = reinterpret_cast<uint4*>(g_hb + (size_t)e * 64 + hf * 32);
            dst[0] = x0; dst[1] = x1; dst[2] = x2; dst[3] = x3;
        }
    }
}

// ---------------- tail: reset counters for next replay ----------------
__global__ void cleanup_kernel() {
    int i = blockIdx.x * 256 + threadIdx.x;
    if (i < NN) { g_deg[i] = 0; g_cursor[i] = 0; }
    if (i < NGR) { g_gcnt[i] = 0; g_gcur[i] = 0; g_flag[i] = 0; }
    if (i == 0) g_done = 0;
}

// ---------------- launch ----------------
extern "C" void kernel_launch(void* const* d_in, const int* in_sizes, int n_in,
                              void* d_out, int out_size) {
    const float* edge_attr = (const float*)d_in[1];
    const int*   eidx      = (const int*)d_in[2];
    const int*   batch     = (const int*)d_in[3];
    const float* nimp      = (const float*)d_in[4];
    const float* W0 = (const float*)d_in[5];
    const float* b0 = (const float*)d_in[6];
    const float* W1 = (const float*)d_in[7];
    const float* b1 = (const float*)d_in[8];
    const float* W2 = (const float*)d_in[9];
    const float* b2 = (const float*)d_in[10];
    float* out = (float*)d_out;

    const int AGG_BLKS = (NN + 7) / 8;

    deg_all<<<EDGE_BLKS + 48 + 3, 256>>>(out, eidx, batch, W0, W1, W2);   // #1
    scanedge_kernel<<<49, 1024>>>(eidx, batch, nimp);                     // #2
    agg1_kernel<<<AGG_BLKS, 256>>>(edge_attr);                            // #3
    fused_kernel<1, true><<<FUS_BLOCKS, 256, SMEM_TOTAL>>>(b0, edge_attr, out);  // #4 <- ncu
    agg64_kernel<<<AGG_BLKS, 256>>>();
    fused_kernel<2, true><<<FUS_BLOCKS, 256, SMEM_TOTAL>>>(b1, nullptr, out);
    agg64_kernel<<<AGG_BLKS, 256>>>();
    fused_kernel<3, false><<<FUS_BLOCKS, 256, SMEM_TOTAL>>>(b2, nullptr, out);
    cleanup_kernel<<<196, 256>>>();
}